// round 11
// baseline (speedup 1.0000x reference)
#include <cuda_runtime.h>
#include <cuda_bf16.h>
#include <cstdint>

#define T_DIM    2048
#define NUM_SEG  64
#define SEG      32
#define F_DIM    32
#define H_DIM    128
#define FEAT_DIM 4
#define SP_PITCH 12

// Precomputed Wh = h @ W_w^T + W_b  (2048 x 32), produced by wh_kernel.
__device__ float g_Wh[T_DIM * F_DIM];

__device__ __forceinline__ uint32_t smem_u32(const void* p) {
    uint32_t a;
    asm("{ .reg .u64 t; cvta.to.shared.u64 t, %1; cvt.u32.u64 %0, t; }" : "=r"(a) : "l"(p));
    return a;
}

__device__ __forceinline__ void bulk_g2s(uint32_t dst, const void* src, uint32_t bytes, uint32_t mbar) {
    asm volatile(
        "cp.async.bulk.shared::cta.global.mbarrier::complete_tx::bytes [%0], [%1], %2, [%3];"
        :: "r"(dst), "l"(src), "r"(bytes), "r"(mbar) : "memory");
}

__device__ __forceinline__ void mbar_wait0(uint32_t mbar) {
    uint32_t done = 0;
    while (!done) {
        asm volatile(
            "{\n\t.reg .pred p;\n\t"
            "mbarrier.try_wait.parity.acquire.cta.shared::cta.b64 p, [%1], 0, 0x989680;\n\t"
            "selp.b32 %0, 1, 0, p;\n\t}"
            : "=r"(done) : "r"(mbar) : "memory");
    }
}

// ---------------------------------------------------------------------------
// Kernel 1: Wh. 128 blocks x 256 threads; 16 rows/block, 2 rows/warp.
// ---------------------------------------------------------------------------
__global__ __launch_bounds__(256, 2)
void wh_kernel(const float* __restrict__ h,
               const float* __restrict__ W_w,
               const float* __restrict__ W_b)
{
    __shared__ float4 Wq_s[F_DIM][33];      // 16.5 KB
    __shared__ float4 hr_s[16][32];         // 8 KB

    const int tid  = threadIdx.x;
    const int row0 = blockIdx.x * 16;
    const int warp = tid >> 5;
    const int lane = tid & 31;

    {
        const float4* w4 = reinterpret_cast<const float4*>(W_w);
        const float4* h4 = reinterpret_cast<const float4*>(h + (size_t)row0 * H_DIM);
        #pragma unroll
        for (int n = tid; n < F_DIM * (H_DIM / 4); n += 256)
            Wq_s[n >> 5][n & 31] = w4[n];
        #pragma unroll
        for (int n = tid; n < 16 * (H_DIM / 4); n += 256)
            hr_s[n >> 5][n & 31] = h4[n];
    }
    __syncthreads();

    const float bias = W_b[lane];
    float acc0 = bias, acc1 = bias;
    #pragma unroll 8
    for (int k4 = 0; k4 < H_DIM / 4; k4++) {
        const float4 w  = Wq_s[lane][k4];
        const float4 a0 = hr_s[warp][k4];
        const float4 a1 = hr_s[warp + 8][k4];
        acc0 += a0.x * w.x + a0.y * w.y + a0.z * w.z + a0.w * w.w;
        acc1 += a1.x * w.x + a1.y * w.y + a1.z * w.z + a1.w * w.w;
    }
    g_Wh[(size_t)(row0 + warp)     * F_DIM + lane] = acc0;
    g_Wh[(size_t)(row0 + warp + 8) * F_DIM + lane] = acc1;
}

// ---------------------------------------------------------------------------
// Kernel 2: attention. 512 blocks x 128 threads; 4 rows/block (1 row/warp).
// PDL: launched overlapping wh_kernel; grid-sync before reading g_Wh.
// ---------------------------------------------------------------------------
__global__ __launch_bounds__(128, 4)
void horizon_attn_kernel(const float* __restrict__ f,
                         const float* __restrict__ h,
                         const float* __restrict__ features,
                         const float* __restrict__ hor,
                         float* __restrict__ S)
{
    __shared__ float4 fs[4][SEG][8];           // 16 KB: 4 f row-blocks, linear
    __shared__ float4 h4_s[SEG][32];           // 16 KB: h_seg
    __shared__ float4 Wh4_s[SEG][8];           // 4 KB : Wh segment rows
    __shared__ float  sp[4][SEG][SP_PITCH];    // 6 KB : per-warp logit partials
    __shared__ alignas(8) unsigned long long mbar1;   // f + h
    __shared__ alignas(8) unsigned long long mbar2;   // Wh

    const int tid  = threadIdx.x;
    const int blk  = blockIdx.x;
    const int seg0 = (blk >> 3) * SEG;         // 8 blocks per segment

    const int warp = tid >> 5;                 // 0..3
    const int lane = tid & 31;

    const int i  = blk * 4 + warp;             // global output row
    const int gj = seg0 + lane;                // lane's segment column

    const uint32_t mb1 = smem_u32(&mbar1);
    const uint32_t mb2 = smem_u32(&mbar2);
    if (tid == 0) {
        asm volatile("mbarrier.init.shared.b64 [%0], 1;" :: "r"(mb1) : "memory");
        asm volatile("mbarrier.init.shared.b64 [%0], 1;" :: "r"(mb2) : "memory");
    }
    __syncthreads();

    // ---- Issue f + h copies NOW (independent of wh_kernel) ----
    if (tid == 0) {
        const uint32_t t1 = 4 * 4096 + 16384;              // 32768 B
        asm volatile("mbarrier.arrive.expect_tx.shared.b64 _, [%0], %1;"
                     :: "r"(mb1), "r"(t1) : "memory");
        #pragma unroll
        for (int r = 0; r < 4; r++)
            bulk_g2s(smem_u32(&fs[r][0][0]),
                     f + ((size_t)(blk * 4 + r) * T_DIM + seg0) * F_DIM,
                     4096, mb1);
        bulk_g2s(smem_u32(&h4_s[0][0]), h + (size_t)seg0 * H_DIM, 16384, mb1);
    }

    // ---- Overlap: mask loads (independent of everything) ----
    const size_t mbi = (size_t)i * T_DIM + gj;
    const float bearing = hor[mbi];
    const float dist    = features[mbi * FEAT_DIM];

    // ---- Wait for wh_kernel to complete, then fetch Wh ----
    cudaGridDependencySynchronize();
    if (tid == 0) {
        asm volatile("mbarrier.arrive.expect_tx.shared.b64 _, [%0], %1;"
                     :: "r"(mb2), "r"(4096u) : "memory");
        bulk_g2s(smem_u32(&Wh4_s[0][0]), g_Wh + (size_t)seg0 * F_DIM, 4096, mb2);
    }

    mbar_wait0(mb1);
    mbar_wait0(mb2);

    // ---- Phase 3: partial logit dots via padded scratch (conflict-free) ----
    float* spw = &sp[warp][0][0];
    {
        const int g = lane >> 3;               // 0..3
        const int c = lane & 7;                // chunk 0..7
        #pragma unroll
        for (int m = 0; m < 8; m++) {
            const int j = 4 * m + g;
            const float4 a = fs[warp][j][c];   // conflict-free per phase
            const float4 w = Wh4_s[j][c];      // conflict-free per phase
            spw[j * SP_PITCH + c] =
                a.x * w.x + a.y * w.y + a.z * w.z + a.w * w.w;   // STS.32 c-free
        }
    }
    __syncwarp();
    const float4 A = *reinterpret_cast<const float4*>(spw + lane * SP_PITCH);
    const float4 B = *reinterpret_cast<const float4*>(spw + lane * SP_PITCH + 4);
    const float logit = (A.x + A.y + A.z + A.w) + (B.x + B.y + B.z + B.w);

    const bool bad = (bearing < 0.f) || (dist > 10.f) || (i == gj);
    const float val = bad ? -1000.f : logit;

    // ---- Phase 4: warp softmax (lane = column j) ----
    float mx = val;
    #pragma unroll
    for (int off = 16; off; off >>= 1)
        mx = fmaxf(mx, __shfl_xor_sync(0xFFFFFFFFu, mx, off));
    const float e = expf(val - mx);
    float ssum = e;
    #pragma unroll
    for (int off = 16; off; off >>= 1)
        ssum += __shfl_xor_sync(0xFFFFFFFFu, ssum, off);
    const float attn = e / ssum;

    // ---- Phase 5: S[i,:] = sum_j attn_j * h_seg[j,:] ----
    float4 Acc = make_float4(0.f, 0.f, 0.f, 0.f);
    #pragma unroll
    for (int jj = 0; jj < SEG; jj++) {
        const float a = __shfl_sync(0xFFFFFFFFu, attn, jj);
        const float4 hv = h4_s[jj][lane];      // conflict-free LDS.128
        Acc.x += a * hv.x;  Acc.y += a * hv.y;
        Acc.z += a * hv.z;  Acc.w += a * hv.w;
    }
    reinterpret_cast<float4*>(S + (size_t)i * H_DIM)[lane] = Acc;   // STG.128
}

extern "C" void kernel_launch(void* const* d_in, const int* in_sizes, int n_in,
                              void* d_out, int out_size)
{
    // metadata order: f, h, features, hor_bearings_MTX, W_w, W_b, sub_batches
    const float* f        = (const float*)d_in[0];
    const float* h        = (const float*)d_in[1];
    const float* features = (const float*)d_in[2];
    const float* hor      = (const float*)d_in[3];
    const float* W_w      = (const float*)d_in[4];
    const float* W_b      = (const float*)d_in[5];
    float* S = (float*)d_out;

    wh_kernel<<<T_DIM / 16, 256>>>(h, W_w, W_b);

    // PDL launch: overlap attn preamble (TMA f/h + mask loads) with wh_kernel.
    cudaLaunchConfig_t cfg = {};
    cfg.gridDim  = dim3(T_DIM / 4, 1, 1);
    cfg.blockDim = dim3(128, 1, 1);
    cudaLaunchAttribute attrs[1];
    attrs[0].id = cudaLaunchAttributeProgrammaticStreamSerialization;
    attrs[0].val.programmaticStreamSerializationAllowed = 1;
    cfg.attrs    = attrs;
    cfg.numAttrs = 1;
    cudaLaunchKernelEx(&cfg, horizon_attn_kernel, f, h, features, hor, S);
}

// round 12
// speedup vs baseline: 1.0172x; 1.0172x over previous
#include <cuda_runtime.h>
#include <cuda_bf16.h>
#include <cstdint>

#define T_DIM    2048
#define NUM_SEG  64
#define SEG      32
#define F_DIM    32
#define H_DIM    128
#define FEAT_DIM 4
#define SP_PITCH 12

// Precomputed Wh = h @ W_w^T + W_b  (2048 x 32), produced by wh_kernel.
__device__ float g_Wh[T_DIM * F_DIM];

__device__ __forceinline__ uint32_t smem_u32(const void* p) {
    uint32_t a;
    asm("{ .reg .u64 t; cvta.to.shared.u64 t, %1; cvt.u32.u64 %0, t; }" : "=r"(a) : "l"(p));
    return a;
}

__device__ __forceinline__ void bulk_g2s(uint32_t dst, const void* src, uint32_t bytes, uint32_t mbar) {
    asm volatile(
        "cp.async.bulk.shared::cta.global.mbarrier::complete_tx::bytes [%0], [%1], %2, [%3];"
        :: "r"(dst), "l"(src), "r"(bytes), "r"(mbar) : "memory");
}

__device__ __forceinline__ void mbar_wait0(uint32_t mbar) {
    uint32_t done = 0;
    while (!done) {
        asm volatile(
            "{\n\t.reg .pred p;\n\t"
            "mbarrier.try_wait.parity.acquire.cta.shared::cta.b64 p, [%1], 0, 0x989680;\n\t"
            "selp.b32 %0, 1, 0, p;\n\t}"
            : "=r"(done) : "r"(mbar) : "memory");
    }
}

// ---------------------------------------------------------------------------
// Kernel 1: Wh. 128 blocks x 256 threads; 16 rows/block, 2 rows/warp.
// ---------------------------------------------------------------------------
__global__ __launch_bounds__(256, 2)
void wh_kernel(const float* __restrict__ h,
               const float* __restrict__ W_w,
               const float* __restrict__ W_b)
{
    __shared__ float4 Wq_s[F_DIM][33];      // 16.5 KB
    __shared__ float4 hr_s[16][32];         // 8 KB

    const int tid  = threadIdx.x;
    const int row0 = blockIdx.x * 16;
    const int warp = tid >> 5;
    const int lane = tid & 31;

    {
        const float4* w4 = reinterpret_cast<const float4*>(W_w);
        const float4* h4 = reinterpret_cast<const float4*>(h + (size_t)row0 * H_DIM);
        #pragma unroll
        for (int n = tid; n < F_DIM * (H_DIM / 4); n += 256)
            Wq_s[n >> 5][n & 31] = w4[n];
        #pragma unroll
        for (int n = tid; n < 16 * (H_DIM / 4); n += 256)
            hr_s[n >> 5][n & 31] = h4[n];
    }
    __syncthreads();

    const float bias = W_b[lane];
    float acc0 = bias, acc1 = bias;
    #pragma unroll 8
    for (int k4 = 0; k4 < H_DIM / 4; k4++) {
        const float4 w  = Wq_s[lane][k4];       // conflict-free LDS.128
        const float4 a0 = hr_s[warp][k4];       // broadcast
        const float4 a1 = hr_s[warp + 8][k4];   // broadcast
        acc0 += a0.x * w.x + a0.y * w.y + a0.z * w.z + a0.w * w.w;
        acc1 += a1.x * w.x + a1.y * w.y + a1.z * w.z + a1.w * w.w;
    }
    g_Wh[(size_t)(row0 + warp)     * F_DIM + lane] = acc0;
    g_Wh[(size_t)(row0 + warp + 8) * F_DIM + lane] = acc1;
}

// ---------------------------------------------------------------------------
// Kernel 2: attention. 512 blocks x 128 threads; 4 rows/block (1 row/warp).
// Stream order guarantees g_Wh is ready -> single mbarrier for all copies.
// Logit reduction via conflict-free sp scratch (no dependent shuffle chains).
// ---------------------------------------------------------------------------
__global__ __launch_bounds__(128, 4)
void horizon_attn_kernel(const float* __restrict__ f,
                         const float* __restrict__ h,
                         const float* __restrict__ features,
                         const float* __restrict__ hor,
                         float* __restrict__ S)
{
    __shared__ float4 fs[4][SEG][8];           // 16 KB: 4 f row-blocks, linear
    __shared__ float4 h4_s[SEG][32];           // 16 KB: h_seg
    __shared__ float4 Wh4_s[SEG][8];           // 4 KB : Wh segment rows
    __shared__ float  sp[4][SEG][SP_PITCH];    // 6 KB : per-warp logit partials
    __shared__ alignas(8) unsigned long long mbar;

    const int tid  = threadIdx.x;
    const int blk  = blockIdx.x;
    const int seg0 = (blk >> 3) * SEG;         // 8 blocks per segment

    const int warp = tid >> 5;                 // 0..3
    const int lane = tid & 31;

    const int i  = blk * 4 + warp;             // global output row
    const int gj = seg0 + lane;                // lane's segment column

    const uint32_t mb = smem_u32(&mbar);
    if (tid == 0) {
        asm volatile("mbarrier.init.shared.b64 [%0], 1;" :: "r"(mb) : "memory");
    }
    __syncthreads();
    if (tid == 0) {
        // f: 4 x 4096 B, h_seg: 16384 B, Wh: 4096 B
        const uint32_t total = 4 * 4096 + 16384 + 4096;   // 36864 B
        asm volatile("mbarrier.arrive.expect_tx.shared.b64 _, [%0], %1;"
                     :: "r"(mb), "r"(total) : "memory");
        #pragma unroll
        for (int r = 0; r < 4; r++)
            bulk_g2s(smem_u32(&fs[r][0][0]),
                     f + ((size_t)(blk * 4 + r) * T_DIM + seg0) * F_DIM,
                     4096, mb);
        bulk_g2s(smem_u32(&h4_s[0][0]),  h + (size_t)seg0 * H_DIM, 16384, mb);
        bulk_g2s(smem_u32(&Wh4_s[0][0]), g_Wh + (size_t)seg0 * F_DIM, 4096, mb);
    }

    // ---- Overlap: per-lane mask loads (independent of smem) ----
    const size_t mbi = (size_t)i * T_DIM + gj;
    const float bearing = hor[mbi];
    const float dist    = features[mbi * FEAT_DIM];

    mbar_wait0(mb);

    // ---- Phase 3: partial logit dots via padded scratch (conflict-free) ----
    float* spw = &sp[warp][0][0];
    {
        const int g = lane >> 3;               // 0..3
        const int c = lane & 7;                // chunk 0..7
        #pragma unroll
        for (int m = 0; m < 8; m++) {
            const int j = 4 * m + g;
            const float4 a = fs[warp][j][c];   // conflict-free per 8-lane phase
            const float4 w = Wh4_s[j][c];      // conflict-free per 8-lane phase
            spw[j * SP_PITCH + c] =
                a.x * w.x + a.y * w.y + a.z * w.z + a.w * w.w;   // STS.32 c-free
        }
    }
    __syncwarp();
    const float4 A = *reinterpret_cast<const float4*>(spw + lane * SP_PITCH);
    const float4 B = *reinterpret_cast<const float4*>(spw + lane * SP_PITCH + 4);
    const float logit = (A.x + A.y + A.z + A.w) + (B.x + B.y + B.z + B.w);

    const bool bad = (bearing < 0.f) || (dist > 10.f) || (i == gj);
    const float val = bad ? -1000.f : logit;

    // ---- Phase 4: warp softmax (lane = column j) ----
    float mx = val;
    #pragma unroll
    for (int off = 16; off; off >>= 1)
        mx = fmaxf(mx, __shfl_xor_sync(0xFFFFFFFFu, mx, off));
    const float e = expf(val - mx);
    float ssum = e;
    #pragma unroll
    for (int off = 16; off; off >>= 1)
        ssum += __shfl_xor_sync(0xFFFFFFFFu, ssum, off);
    const float attn = e / ssum;

    // ---- Phase 5: S[i,:] = sum_j attn_j * h_seg[j,:] ----
    float4 Acc = make_float4(0.f, 0.f, 0.f, 0.f);
    #pragma unroll
    for (int jj = 0; jj < SEG; jj++) {
        const float a = __shfl_sync(0xFFFFFFFFu, attn, jj);
        const float4 hv = h4_s[jj][lane];      // conflict-free LDS.128
        Acc.x += a * hv.x;  Acc.y += a * hv.y;
        Acc.z += a * hv.z;  Acc.w += a * hv.w;
    }
    reinterpret_cast<float4*>(S + (size_t)i * H_DIM)[lane] = Acc;   // STG.128
}

extern "C" void kernel_launch(void* const* d_in, const int* in_sizes, int n_in,
                              void* d_out, int out_size)
{
    // metadata order: f, h, features, hor_bearings_MTX, W_w, W_b, sub_batches
    const float* f        = (const float*)d_in[0];
    const float* h        = (const float*)d_in[1];
    const float* features = (const float*)d_in[2];
    const float* hor      = (const float*)d_in[3];
    const float* W_w      = (const float*)d_in[4];
    const float* W_b      = (const float*)d_in[5];
    float* S = (float*)d_out;

    wh_kernel<<<T_DIM / 16, 256>>>(h, W_w, W_b);
    horizon_attn_kernel<<<T_DIM / 4, 128>>>(f, h, features, hor, S);
}

// round 14
// speedup vs baseline: 1.1830x; 1.1629x over previous
#include <cuda_runtime.h>
#include <cuda_bf16.h>
#include <cstdint>

#define T_DIM    2048
#define NUM_SEG  64
#define SEG      32
#define F_DIM    32
#define H_DIM    128
#define FEAT_DIM 4

// Precomputed Wh = h @ W_w^T + W_b  (2048 x 32), produced by wh_kernel.
__device__ float g_Wh[T_DIM * F_DIM];

__device__ __forceinline__ uint32_t smem_u32(const void* p) {
    uint32_t a;
    asm("{ .reg .u64 t; cvta.to.shared.u64 t, %1; cvt.u32.u64 %0, t; }" : "=r"(a) : "l"(p));
    return a;
}

__device__ __forceinline__ void bulk_g2s(uint32_t dst, const void* src, uint32_t bytes, uint32_t mbar) {
    asm volatile(
        "cp.async.bulk.shared::cta.global.mbarrier::complete_tx::bytes [%0], [%1], %2, [%3];"
        :: "r"(dst), "l"(src), "r"(bytes), "r"(mbar) : "memory");
}

__device__ __forceinline__ void mbar_wait0(uint32_t mbar) {
    uint32_t done = 0;
    while (!done) {
        asm volatile(
            "{\n\t.reg .pred p;\n\t"
            "mbarrier.try_wait.parity.acquire.cta.shared::cta.b64 p, [%1], 0, 0x989680;\n\t"
            "selp.b32 %0, 1, 0, p;\n\t}"
            : "=r"(done) : "r"(mbar) : "memory");
    }
}

// ---------------------------------------------------------------------------
// Kernel 1: Wh. 128 blocks x 256 threads; 16 rows/block, 2 rows/warp.
// ---------------------------------------------------------------------------
__global__ __launch_bounds__(256, 2)
void wh_kernel(const float* __restrict__ h,
               const float* __restrict__ W_w,
               const float* __restrict__ W_b)
{
    __shared__ float4 Wq_s[F_DIM][33];      // 16.5 KB
    __shared__ float4 hr_s[16][32];         // 8 KB

    const int tid  = threadIdx.x;
    const int row0 = blockIdx.x * 16;
    const int warp = tid >> 5;
    const int lane = tid & 31;

    {
        const float4* w4 = reinterpret_cast<const float4*>(W_w);
        const float4* h4 = reinterpret_cast<const float4*>(h + (size_t)row0 * H_DIM);
        #pragma unroll
        for (int n = tid; n < F_DIM * (H_DIM / 4); n += 256)
            Wq_s[n >> 5][n & 31] = w4[n];
        #pragma unroll
        for (int n = tid; n < 16 * (H_DIM / 4); n += 256)
            hr_s[n >> 5][n & 31] = h4[n];
    }
    __syncthreads();

    const float bias = W_b[lane];
    float acc0 = bias, acc1 = bias;
    #pragma unroll 8
    for (int k4 = 0; k4 < H_DIM / 4; k4++) {
        const float4 w  = Wq_s[lane][k4];
        const float4 a0 = hr_s[warp][k4];
        const float4 a1 = hr_s[warp + 8][k4];
        acc0 += a0.x * w.x + a0.y * w.y + a0.z * w.z + a0.w * w.w;
        acc1 += a1.x * w.x + a1.y * w.y + a1.z * w.z + a1.w * w.w;
    }
    g_Wh[(size_t)(row0 + warp)     * F_DIM + lane] = acc0;
    g_Wh[(size_t)(row0 + warp + 8) * F_DIM + lane] = acc1;
}

// ---------------------------------------------------------------------------
// Kernel 2: attention. 512 blocks x 128 threads; 4 rows/block (1 row/warp).
// mb1 = f + Wh (logit inputs), mb2 = h (phase-5 input) for finer overlap.
// Phase 5 is column-sliced across warps (1-wavefront LDS, no shuffles).
// ---------------------------------------------------------------------------
__global__ __launch_bounds__(128, 4)
void horizon_attn_kernel(const float* __restrict__ f,
                         const float* __restrict__ h,
                         const float* __restrict__ features,
                         const float* __restrict__ hor,
                         float* __restrict__ S)
{
    __shared__ float4 fs[4][SEG][8];        // 16 KB: 4 f row-blocks, linear
    __shared__ float4 h4_s[SEG][32];        // 16 KB: h_seg
    __shared__ float4 Wh4_s[SEG][8];        // 4 KB : Wh segment rows
    __shared__ float  attn_s[4][SEG];       // 512 B: attn rows for phase 5
    __shared__ alignas(8) unsigned long long mbar1;   // f + Wh
    __shared__ alignas(8) unsigned long long mbar2;   // h

    const int tid  = threadIdx.x;
    const int blk  = blockIdx.x;
    const int seg0 = (blk >> 3) * SEG;      // 8 blocks per segment

    const int warp = tid >> 5;              // 0..3  (output row within block)
    const int lane = tid & 31;

    const int i  = blk * 4 + warp;          // global output row
    const int gj = seg0 + lane;             // lane's segment column

    const uint32_t mb1 = smem_u32(&mbar1);
    const uint32_t mb2 = smem_u32(&mbar2);
    if (tid == 0) {
        asm volatile("mbarrier.init.shared.b64 [%0], 1;" :: "r"(mb1) : "memory");
        asm volatile("mbarrier.init.shared.b64 [%0], 1;" :: "r"(mb2) : "memory");
    }
    __syncthreads();
    if (tid == 0) {
        asm volatile("mbarrier.arrive.expect_tx.shared.b64 _, [%0], %1;"
                     :: "r"(mb1), "r"(4u * 4096u + 4096u) : "memory");   // 20480 B
        bulk_g2s(smem_u32(&Wh4_s[0][0]), g_Wh + (size_t)seg0 * F_DIM, 4096, mb1);
        #pragma unroll
        for (int r = 0; r < 4; r++)
            bulk_g2s(smem_u32(&fs[r][0][0]),
                     f + ((size_t)(blk * 4 + r) * T_DIM + seg0) * F_DIM,
                     4096, mb1);
        asm volatile("mbarrier.arrive.expect_tx.shared.b64 _, [%0], %1;"
                     :: "r"(mb2), "r"(16384u) : "memory");
        bulk_g2s(smem_u32(&h4_s[0][0]), h + (size_t)seg0 * H_DIM, 16384, mb2);
    }

    // ---- Overlap: per-lane mask loads (independent of smem) ----
    const size_t mbi = (size_t)i * T_DIM + gj;
    const float bearing = hor[mbi];
    const float dist    = features[mbi * FEAT_DIM];
    const float badf = ((bearing < 0.f) || (dist > 10.f) || (i == gj)) ? 1.f : 0.f;

    // ---- Wait for logit inputs only ----
    mbar_wait0(mb1);

    // ---- Partial logit dots: lane l -> chunk c=l&7 of row j=4m+(l>>3) ----
    const int g = lane >> 3;
    const int c = lane & 7;
    float val[8];
    #pragma unroll
    for (int m = 0; m < 8; m++) {
        const int j = 4 * m + g;
        const float4 a = fs[warp][j][c];
        const float4 w = Wh4_s[j][c];
        float p = a.x * w.x + a.y * w.y + a.z * w.z + a.w * w.w;
        p += __shfl_xor_sync(0xFFFFFFFFu, p, 1);
        p += __shfl_xor_sync(0xFFFFFFFFu, p, 2);
        p += __shfl_xor_sync(0xFFFFFFFFu, p, 4);
        const float bm = __shfl_sync(0xFFFFFFFFu, badf, j);
        val[m] = (bm != 0.f) ? -1000.f : p;
    }

    // ---- Softmax over 32 columns (each replicated on 8 lanes) ----
    float mx = val[0];
    #pragma unroll
    for (int m = 1; m < 8; m++) mx = fmaxf(mx, val[m]);
    #pragma unroll
    for (int off = 16; off; off >>= 1)
        mx = fmaxf(mx, __shfl_xor_sync(0xFFFFFFFFu, mx, off));

    float e[8];
    float ls = 0.f;
    #pragma unroll
    for (int m = 0; m < 8; m++) { e[m] = expf(val[m] - mx); ls += e[m]; }
    #pragma unroll
    for (int off = 16; off; off >>= 1)
        ls += __shfl_xor_sync(0xFFFFFFFFu, ls, off);
    const float inv = 8.f / ls;              // ls = 8 * true_sum

    // ---- Publish attn row: lane l stores col 4c+g (distinct mod 32) ----
    attn_s[warp][4 * c + g] = e[c] * inv;    // attn[row=warp][col=4c+g] = e[m=c]
    __syncthreads();

    // ---- Wait for h, then column-sliced phase 5 ----
    mbar_wait0(mb2);

    // lane l: row r = l>>3, col-chunk cc = warp*8 + (l&7) (float4 index)
    const int r  = lane >> 3;
    const int cc = warp * 8 + (lane & 7);
    float4 Acc = make_float4(0.f, 0.f, 0.f, 0.f);
    #pragma unroll
    for (int jj = 0; jj < SEG; jj++) {
        const float a = attn_s[r][jj];       // 4 distinct addrs -> broadcast, 1 cyc
        const float4 hv = h4_s[jj][cc];      // 8 distinct float4 -> 1 wavefront
        Acc.x += a * hv.x;  Acc.y += a * hv.y;
        Acc.z += a * hv.z;  Acc.w += a * hv.w;
    }
    // S[blk*4 + r][4cc .. 4cc+3]
    reinterpret_cast<float4*>(S + (size_t)(blk * 4 + r) * H_DIM)[cc] = Acc;
}

extern "C" void kernel_launch(void* const* d_in, const int* in_sizes, int n_in,
                              void* d_out, int out_size)
{
    // metadata order: f, h, features, hor_bearings_MTX, W_w, W_b, sub_batches
    const float* f        = (const float*)d_in[0];
    const float* h        = (const float*)d_in[1];
    const float* features = (const float*)d_in[2];
    const float* hor      = (const float*)d_in[3];
    const float* W_w      = (const float*)d_in[4];
    const float* W_b      = (const float*)d_in[5];
    float* S = (float*)d_out;

    wh_kernel<<<T_DIM / 16, 256>>>(h, W_w, W_b);
    horizon_attn_kernel<<<T_DIM / 4, 128>>>(f, h, features, hor, S);
}

// round 15
// speedup vs baseline: 1.3721x; 1.1599x over previous
#include <cuda_runtime.h>
#include <cuda_bf16.h>
#include <cstdint>

#define T_DIM    2048
#define NUM_SEG  64
#define SEG      32
#define F_DIM    32
#define H_DIM    128
#define FEAT_DIM 4

#define RPB      8                       // rows per block (1 per warp)
#define ATHREADS 256                     // 8 warps
#define AGRID    (T_DIM / RPB)           // 256 blocks

// Dynamic smem layout (bytes):
//   fs   : [RPB][SEG][8] float4   = 32768
//   h4_s : [SEG][32]     float4   = 16384   (offset 32768)
//   Wh4_s: [SEG][8]      float4   =  4096   (offset 49152)
//   mbar : u64                     (offset 53248)
#define OFF_H    32768
#define OFF_WH   49152
#define OFF_MBAR 53248
#define SMEM_TOTAL 53256

// Precomputed Wh = h @ W_w^T + W_b  (2048 x 32), produced by wh_kernel.
__device__ float g_Wh[T_DIM * F_DIM];

__device__ __forceinline__ uint32_t smem_u32(const void* p) {
    uint32_t a;
    asm("{ .reg .u64 t; cvta.to.shared.u64 t, %1; cvt.u32.u64 %0, t; }" : "=r"(a) : "l"(p));
    return a;
}

__device__ __forceinline__ void bulk_g2s(uint32_t dst, const void* src, uint32_t bytes, uint32_t mbar) {
    asm volatile(
        "cp.async.bulk.shared::cta.global.mbarrier::complete_tx::bytes [%0], [%1], %2, [%3];"
        :: "r"(dst), "l"(src), "r"(bytes), "r"(mbar) : "memory");
}

__device__ __forceinline__ void mbar_wait0(uint32_t mbar) {
    uint32_t done = 0;
    while (!done) {
        asm volatile(
            "{\n\t.reg .pred p;\n\t"
            "mbarrier.try_wait.parity.acquire.cta.shared::cta.b64 p, [%1], 0, 0x989680;\n\t"
            "selp.b32 %0, 1, 0, p;\n\t}"
            : "=r"(done) : "r"(mbar) : "memory");
    }
}

// ---------------------------------------------------------------------------
// Kernel 1: Wh. 128 blocks x 256 threads; 16 rows/block, 2 rows/warp.
// (unchanged, verified)
// ---------------------------------------------------------------------------
__global__ __launch_bounds__(256, 2)
void wh_kernel(const float* __restrict__ h,
               const float* __restrict__ W_w,
               const float* __restrict__ W_b)
{
    __shared__ float4 Wq_s[F_DIM][33];      // 16.5 KB
    __shared__ float4 hr_s[16][32];         // 8 KB

    const int tid  = threadIdx.x;
    const int row0 = blockIdx.x * 16;
    const int warp = tid >> 5;
    const int lane = tid & 31;

    {
        const float4* w4 = reinterpret_cast<const float4*>(W_w);
        const float4* h4 = reinterpret_cast<const float4*>(h + (size_t)row0 * H_DIM);
        #pragma unroll
        for (int n = tid; n < F_DIM * (H_DIM / 4); n += 256)
            Wq_s[n >> 5][n & 31] = w4[n];
        #pragma unroll
        for (int n = tid; n < 16 * (H_DIM / 4); n += 256)
            hr_s[n >> 5][n & 31] = h4[n];
    }
    __syncthreads();

    const float bias = W_b[lane];
    float acc0 = bias, acc1 = bias;
    #pragma unroll 8
    for (int k4 = 0; k4 < H_DIM / 4; k4++) {
        const float4 w  = Wq_s[lane][k4];
        const float4 a0 = hr_s[warp][k4];
        const float4 a1 = hr_s[warp + 8][k4];
        acc0 += a0.x * w.x + a0.y * w.y + a0.z * w.z + a0.w * w.w;
        acc1 += a1.x * w.x + a1.y * w.y + a1.z * w.z + a1.w * w.w;
    }
    g_Wh[(size_t)(row0 + warp)     * F_DIM + lane] = acc0;
    g_Wh[(size_t)(row0 + warp + 8) * F_DIM + lane] = acc1;
}

// ---------------------------------------------------------------------------
// Kernel 2: attention. 256 blocks x 256 threads; 8 rows/block (1 row/warp).
// R10 compute verbatim; h/Wh staged once per 8 rows (TMA bytes -28%).
// ---------------------------------------------------------------------------
__global__ __launch_bounds__(ATHREADS, 1)
void horizon_attn_kernel(const float* __restrict__ f,
                         const float* __restrict__ h,
                         const float* __restrict__ features,
                         const float* __restrict__ hor,
                         float* __restrict__ S)
{
    extern __shared__ char smem[];
    float4* fs    = reinterpret_cast<float4*>(smem);             // [RPB][SEG][8]
    float4* h4_s  = reinterpret_cast<float4*>(smem + OFF_H);     // [SEG][32]
    float4* Wh4_s = reinterpret_cast<float4*>(smem + OFF_WH);    // [SEG][8]

    const int tid  = threadIdx.x;
    const int blk  = blockIdx.x;
    const int seg0 = (blk >> 2) * SEG;      // 4 blocks per segment

    const int warp = tid >> 5;              // 0..7
    const int lane = tid & 31;

    const int i  = blk * RPB + warp;        // global output row
    const int gj = seg0 + lane;             // lane's segment column

    const uint32_t mb = smem_u32(smem + OFF_MBAR);
    if (tid == 0) {
        asm volatile("mbarrier.init.shared.b64 [%0], 1;" :: "r"(mb) : "memory");
    }
    __syncthreads();
    if (tid == 0) {
        // f: RPB x 4096, h: 16384, Wh: 4096  => 53248 B
        const uint32_t total = RPB * 4096 + 16384 + 4096;
        asm volatile("mbarrier.arrive.expect_tx.shared.b64 _, [%0], %1;"
                     :: "r"(mb), "r"(total) : "memory");
        #pragma unroll
        for (int r = 0; r < RPB; r++)
            bulk_g2s(smem_u32(fs + (size_t)r * SEG * 8),
                     f + ((size_t)(blk * RPB + r) * T_DIM + seg0) * F_DIM,
                     4096, mb);
        bulk_g2s(smem_u32(h4_s),  h + (size_t)seg0 * H_DIM, 16384, mb);
        bulk_g2s(smem_u32(Wh4_s), g_Wh + (size_t)seg0 * F_DIM, 4096, mb);
    }

    // ---- Overlap: per-lane mask loads (independent of smem) ----
    const size_t mbi = (size_t)i * T_DIM + gj;
    const float bearing = hor[mbi];
    const float dist    = features[mbi * FEAT_DIM];
    const float badf = ((bearing < 0.f) || (dist > 10.f) || (i == gj)) ? 1.f : 0.f;

    mbar_wait0(mb);

    // ---- Partial logit dots: lane l -> chunk c=l&7 of row j=4m+(l>>3) ----
    const int g = lane >> 3;
    const int c = lane & 7;
    const float4* fw = fs + (size_t)warp * SEG * 8;
    float val[8];
    #pragma unroll
    for (int m = 0; m < 8; m++) {
        const int j = 4 * m + g;
        const float4 a = fw[j * 8 + c];     // 128B contiguous per 8-lane phase
        const float4 w = Wh4_s[j * 8 + c];  // 128B contiguous per 8-lane phase
        float p = a.x * w.x + a.y * w.y + a.z * w.z + a.w * w.w;
        p += __shfl_xor_sync(0xFFFFFFFFu, p, 1);
        p += __shfl_xor_sync(0xFFFFFFFFu, p, 2);
        p += __shfl_xor_sync(0xFFFFFFFFu, p, 4);
        const float bm = __shfl_sync(0xFFFFFFFFu, badf, j);
        val[m] = (bm != 0.f) ? -1000.f : p;
    }

    // ---- Softmax over 32 columns (each replicated on 8 lanes) ----
    float mx = val[0];
    #pragma unroll
    for (int m = 1; m < 8; m++) mx = fmaxf(mx, val[m]);
    #pragma unroll
    for (int off = 16; off; off >>= 1)
        mx = fmaxf(mx, __shfl_xor_sync(0xFFFFFFFFu, mx, off));

    float e[8];
    float ls = 0.f;
    #pragma unroll
    for (int m = 0; m < 8; m++) { e[m] = expf(val[m] - mx); ls += e[m]; }
    #pragma unroll
    for (int off = 16; off; off >>= 1)
        ls += __shfl_xor_sync(0xFFFFFFFFu, ls, off);
    const float inv = 8.f / ls;             // ls = 8 * true_sum
    #pragma unroll
    for (int m = 0; m < 8; m++) e[m] *= inv;   // e[m] = attn[4m+g]

    // ---- S[i,:] = sum_j attn_j * h_seg[j,:]; lane owns 4 contiguous cols ----
    float4 Acc = make_float4(0.f, 0.f, 0.f, 0.f);
    #pragma unroll
    for (int jj = 0; jj < SEG; jj++) {
        const float a = __shfl_sync(0xFFFFFFFFu, e[jj >> 2], (jj & 3) * 8);
        const float4 hv = h4_s[jj * 32 + lane];   // conflict-free LDS.128
        Acc.x += a * hv.x;  Acc.y += a * hv.y;
        Acc.z += a * hv.z;  Acc.w += a * hv.w;
    }
    reinterpret_cast<float4*>(S + (size_t)i * H_DIM)[lane] = Acc;   // STG.128
}

extern "C" void kernel_launch(void* const* d_in, const int* in_sizes, int n_in,
                              void* d_out, int out_size)
{
    // metadata order: f, h, features, hor_bearings_MTX, W_w, W_b, sub_batches
    const float* f        = (const float*)d_in[0];
    const float* h        = (const float*)d_in[1];
    const float* features = (const float*)d_in[2];
    const float* hor      = (const float*)d_in[3];
    const float* W_w      = (const float*)d_in[4];
    const float* W_b      = (const float*)d_in[5];
    float* S = (float*)d_out;

    cudaFuncSetAttribute(horizon_attn_kernel,
                         cudaFuncAttributeMaxDynamicSharedMemorySize, SMEM_TOTAL);

    wh_kernel<<<T_DIM / 16, 256>>>(h, W_w, W_b);
    horizon_attn_kernel<<<AGRID, ATHREADS, SMEM_TOTAL>>>(f, h, features, hor, S);
}